// round 3
// baseline (speedup 1.0000x reference)
#include <cuda_runtime.h>
#include <cuda_bf16.h>
#include <cstdint>

// Problem constants
#define T_ 8
#define L_ 8
#define N_ 500
#define D_ 64
#define K_ 12
#define S_ 2
#define RLN (L_*N_)          // 4000
#define R_ (T_*L_*N_)        // 32000 rows of (t,l,n)
#define ELEMS (R_*D_)        // 2048000

typedef unsigned long long ull;

// ---------------- scratch buffers (no allocation allowed) ----------------
__device__ float g_dyn[ELEMS];          // all_dyn (T,L,N,D)
__device__ float g_q6[6][ELEMS];        // q per (branch,graph)
__device__ float g_k6[6][ELEMS];        // k per (branch,graph)
__device__ float g_x6[6][ELEMS];        // attention output per (branch,graph)
__device__ float g_mixb[2][ELEMS];      // mixed dyn / sta
__device__ float g_h[T_*N_];            // LSTM h_last

__device__ __forceinline__ float sigf(float x) {
    return 1.f / (1.f + __expf(-x));
}

// packed dual-fp32 FMA: acc.{lo,hi} += a.{lo,hi} * b.{lo,hi}
__device__ __forceinline__ void fma2(ull& acc, ull a, ull b) {
    asm("fma.rn.f32x2 %0, %1, %2, %0;" : "+l"(acc) : "l"(a), "l"(b));
}
__device__ __forceinline__ float lo32(ull v) { return __uint_as_float((unsigned)v); }
__device__ __forceinline__ float hi32(ull v) { return __uint_as_float((unsigned)(v >> 32)); }

// =====================================================================
// 1. evolution scan: grid 250, block 256 (64 lanes x 4 groups x 4 rows)
// =====================================================================
__global__ void evo_kernel(const float* __restrict__ stat,
                           const float* __restrict__ thre,
                           const float* __restrict__ dynn,
                           const float* __restrict__ w1,
                           float* __restrict__ out_nowfinal,
                           float* __restrict__ out_diffs) {
    __shared__ float w1T[64 * 132];       // w1T[e][d], d 0..127
    __shared__ float now_s[16][64];
    __shared__ float st_s[16][64];
    __shared__ float th_s[16];
    int tid = threadIdx.x;
    for (int i = tid; i < 8192; i += 256) {
        int d = i >> 6, e = i & 63;
        w1T[e * 132 + d] = w1[i];
    }
    int e = tid & 63, grp = tid >> 6;
    int row0 = blockIdx.x * 16;
#pragma unroll
    for (int i = 0; i < 4; i++) {
        int r = grp * 4 + i;
        float v = dynn[(size_t)(row0 + r) * 64 + e];
        now_s[r][e] = v;
        g_dyn[(size_t)(row0 + r) * 64 + e] = v;   // all_dyn[t=0]
    }
    __syncthreads();

    for (int t = 1; t < T_; t++) {
        size_t base = (size_t)t * RLN + row0;
        ((float4*)st_s)[tid] = ((const float4*)(stat + base * 64))[tid];
        if (tid < 16) th_s[tid] = thre[base + tid];
        __syncthreads();

        float sum[4] = {0.f, 0.f, 0.f, 0.f};
#pragma unroll
        for (int d = 0; d < 64; d += 4) {
            float4 wn = *(float4*)&w1T[e * 132 + d];
            float4 ws = *(float4*)&w1T[e * 132 + 64 + d];
#pragma unroll
            for (int i = 0; i < 4; i++) {
                float4 nv = *(float4*)&now_s[grp * 4 + i][d];
                float4 sv = *(float4*)&st_s[grp * 4 + i][d];
                sum[i] += nv.x * wn.x + nv.y * wn.y + nv.z * wn.z + nv.w * wn.w
                        + sv.x * ws.x + sv.y * ws.y + sv.z * ws.z + sv.w * ws.w;
            }
        }
        float vals[4];
#pragma unroll
        for (int i = 0; i < 4; i++) {
            int r = grp * 4 + i;
            float th = th_s[r];
            float nv = now_s[r][e];
            float val = sigf(sum[i] * th + nv * (1.f - th));
            vals[i] = val;
            g_dyn[(base + r) * 64 + e] = val;
            out_diffs[((size_t)(t - 1) * RLN + row0 + r) * 64 + e] = val - nv;
            if (t == T_ - 1) out_nowfinal[(size_t)(row0 + r) * 64 + e] = val;
        }
        __syncthreads();
#pragma unroll
        for (int i = 0; i < 4; i++) now_s[grp * 4 + i][e] = vals[i];
        __syncthreads();
    }
}

// =====================================================================
// 2. pass1: q/k GEMM with packed f32x2 FMAs. grid 1500, block 512.
//    C[128 rows x 128 cols(q|k)] = X[128x64] @ [wq|wk]
//    acc pairs over ROWS (from transposed A), weights dup'd in smem.
// =====================================================================
#define AT_PITCH 136
#define WD_PITCH 132
#define P1_SMEM ((64*AT_PITCH)*4 + (64*WD_PITCH)*8)   // 34816 + 67584 = 102400

__global__ void __launch_bounds__(512, 2)
pass1_kernel(const float* __restrict__ stat,
             const float* __restrict__ wq_all,
             const float* __restrict__ wk_all,
             int s) {
    extern __shared__ float sm[];
    float* At = sm;                              // [64][AT_PITCH] transposed X
    float2* Wd = (float2*)(sm + 64 * AT_PITCH);  // [64][WD_PITCH] dup'd weights
    float* A_nat = (float*)Wd;                   // [128][68] transient staging
    int tid = threadIdx.x;
    int bg = blockIdx.x / 250;
    int blk = blockIdx.x - bg * 250;

    const float* src;
    if (s == 0) src = (bg < 3) ? (const float*)g_dyn : stat;
    else        src = g_x6[bg];
    const float4* x4 = (const float4*)(src + (size_t)blk * 128 * 64);

    // phase 1: coalesced load X into A_nat (lives in Wd's space)
    for (int i = tid; i < 2048; i += 512) {
        int row = i >> 4, c4 = (i & 15) << 2;
        *(float4*)&A_nat[row * 68 + c4] = x4[i];
    }
    __syncthreads();
    // phase 2: transpose into At
    {
        int k = tid & 63, rg = tid >> 6;
#pragma unroll
        for (int r16 = 0; r16 < 16; r16++) {
            int row = rg * 16 + r16;
            At[k * AT_PITCH + row] = A_nat[row * 68 + k];
        }
    }
    __syncthreads();
    // phase 3: stage dup'd weights (overwrites A_nat)
    {
        const float4* wq4 = (const float4*)(wq_all + (size_t)(bg * 2 + s) * 4096);
        const float4* wk4 = (const float4*)(wk_all + (size_t)(bg * 2 + s) * 4096);
        for (int i = tid; i < 2048; i += 512) {
            int half = i >> 10, idx = i & 1023;
            int k = idx >> 4, c4 = (idx & 15) << 2;
            float4 v = half ? wk4[idx] : wq4[idx];
            float2* dst = &Wd[k * WD_PITCH + half * 64 + c4];
            dst[0] = make_float2(v.x, v.x);
            dst[1] = make_float2(v.y, v.y);
            dst[2] = make_float2(v.z, v.z);
            dst[3] = make_float2(v.w, v.w);
        }
    }
    __syncthreads();

    int tx = tid & 31, ty = tid >> 5;   // tx: col group, ty: row group (8 rows)
    ull acc[4][4];
#pragma unroll
    for (int i = 0; i < 4; i++)
#pragma unroll
        for (int j = 0; j < 4; j++) acc[i][j] = 0ull;

    const ull* WdU = (const ull*)Wd;
#pragma unroll 4
    for (int k = 0; k < 64; k++) {
        // row pairs (broadcast within warp: whole warp shares ty)
        ulonglong2 a01 = *(const ulonglong2*)&At[k * AT_PITCH + ty * 8];
        ulonglong2 a23 = *(const ulonglong2*)&At[k * AT_PITCH + ty * 8 + 4];
        // dup'd weight cols: tx, tx+32 (q), tx+64, tx+96 (k)
        ull b0 = WdU[k * WD_PITCH + tx];
        ull b1 = WdU[k * WD_PITCH + tx + 32];
        ull b2 = WdU[k * WD_PITCH + tx + 64];
        ull b3 = WdU[k * WD_PITCH + tx + 96];
        fma2(acc[0][0], a01.x, b0); fma2(acc[0][1], a01.x, b1);
        fma2(acc[0][2], a01.x, b2); fma2(acc[0][3], a01.x, b3);
        fma2(acc[1][0], a01.y, b0); fma2(acc[1][1], a01.y, b1);
        fma2(acc[1][2], a01.y, b2); fma2(acc[1][3], a01.y, b3);
        fma2(acc[2][0], a23.x, b0); fma2(acc[2][1], a23.x, b1);
        fma2(acc[2][2], a23.x, b2); fma2(acc[2][3], a23.x, b3);
        fma2(acc[3][0], a23.y, b0); fma2(acc[3][1], a23.y, b1);
        fma2(acc[3][2], a23.y, b2); fma2(acc[3][3], a23.y, b3);
    }

    float* qdst = g_q6[bg];
    float* kdst = g_k6[bg];
    size_t rowbase = (size_t)blk * 128 + ty * 8;
#pragma unroll
    for (int ip = 0; ip < 4; ip++) {
        size_t r0 = (rowbase + 2 * ip) * 64;
        size_t r1 = r0 + 64;
#pragma unroll
        for (int j = 0; j < 4; j++) {
            int c = tx + 32 * (j & 1);
            float* dst = (j < 2) ? qdst : kdst;
            dst[r0 + c] = lo32(acc[ip][j]);
            dst[r1 + c] = hi32(acc[ip][j]);
        }
    }
}

// =====================================================================
// 3. pass2: gather + softmax attention + wd + sigmoid. grid 6000, block 256.
//    Phase A: 16-lane x 4-elem layout; output stored DUP'd (float2{o,o}).
//    Phase B: f32x2 GEMM vs natural wd col-pairs.
// =====================================================================
#define OD_PITCH 68
__global__ void __launch_bounds__(256)
pass2_kernel(const int* __restrict__ n0,
             const int* __restrict__ n1,
             const int* __restrict__ n2,
             const float* __restrict__ wd_all,
             int s) {
    __shared__ float wd_s[64 * 64];              // natural
    __shared__ float2 outD[8][4][OD_PITCH];      // dup'd attention output
    int tid = threadIdx.x;
    int bg = blockIdx.x / 1000;
    int blk = blockIdx.x - bg * 1000;
    int gi3 = bg % 3;
    const int* neigh = (gi3 == 0) ? n0 : (gi3 == 1) ? n1 : n2;
    const float* wd = wd_all + (size_t)(bg * 2 + s) * 4096;

    for (int i = tid; i < 4096; i += 256) wd_s[i] = wd[i];
    __syncthreads();

    int w = tid >> 5, lane = tid & 31;
    int half = lane >> 4, l16 = lane & 15;
    const float* qb = g_q6[bg];
    const float* kb = g_k6[bg];

    // Phase A: 4 rows per warp as 2 pairs (one row per 16-lane half)
#pragma unroll
    for (int pr = 0; pr < 2; pr++) {
        int r = pr * 2 + half;
        int rowid = blk * 32 + w * 4 + r;
        int tl = rowid / N_;
        int n = rowid - tl * N_;
        const float* krow_base = kb + (size_t)tl * N_ * 64;
        float4 q = *(const float4*)&qb[(size_t)rowid * 64 + l16 * 4];
        float dots[K_];
        int nbs[K_];
#pragma unroll
        for (int j = 0; j < K_; j++) {
            int nb = __ldg(&neigh[n * K_ + j]);
            nbs[j] = nb;
            float4 kv = *(const float4*)&krow_base[(size_t)nb * 64 + l16 * 4];
            float d = q.x * kv.x + q.y * kv.y + q.z * kv.z + q.w * kv.w;
            d += __shfl_xor_sync(0xffffffffu, d, 8);
            d += __shfl_xor_sync(0xffffffffu, d, 4);
            d += __shfl_xor_sync(0xffffffffu, d, 2);
            d += __shfl_xor_sync(0xffffffffu, d, 1);
            dots[j] = d;
        }
        float m = dots[0];
#pragma unroll
        for (int j = 1; j < K_; j++) m = fmaxf(m, dots[j]);
        float ssum = 0.f;
#pragma unroll
        for (int j = 0; j < K_; j++) {
            dots[j] = __expf(dots[j] - m);
            ssum += dots[j];
        }
        float inv = 1.f / ssum;
        float4 o = q;
#pragma unroll
        for (int j = 0; j < K_; j++) {
            float a = dots[j] * inv;
            float4 kv = *(const float4*)&krow_base[(size_t)nbs[j] * 64 + l16 * 4];
            o.x = fmaf(a, kv.x, o.x);
            o.y = fmaf(a, kv.y, o.y);
            o.z = fmaf(a, kv.z, o.z);
            o.w = fmaf(a, kv.w, o.w);
        }
        float2* ob = &outD[w][r][l16 * 4];
        ob[0] = make_float2(o.x, o.x);
        ob[1] = make_float2(o.y, o.y);
        ob[2] = make_float2(o.z, o.z);
        ob[3] = make_float2(o.w, o.w);
    }
    __syncwarp();

    // Phase B: out @ wd with f32x2; lane owns cols (2*lane, 2*lane+1), 4 rows
    ull acc2[4] = {0ull, 0ull, 0ull, 0ull};
#pragma unroll 8
    for (int d = 0; d < 64; d += 2) {
        ull w0 = *(const ull*)&wd_s[d * 64 + lane * 2];
        ull w1 = *(const ull*)&wd_s[(d + 1) * 64 + lane * 2];
#pragma unroll
        for (int r = 0; r < 4; r++) {
            ulonglong2 ov = *(const ulonglong2*)&outD[w][r][d];
            fma2(acc2[r], ov.x, w0);
            fma2(acc2[r], ov.y, w1);
        }
    }
    float* xdst = g_x6[bg];
#pragma unroll
    for (int r = 0; r < 4; r++) {
        int rowid = blk * 32 + w * 4 + r;
        float2 v = make_float2(sigf(lo32(acc2[r])), sigf(hi32(acc2[r])));
        *(float2*)&xdst[(size_t)rowid * 64 + lane * 2] = v;
    }
}

// =====================================================================
// 4. mix: g_mixb[b] = sigmoid(sum_g x6[b*3+g] * wmix[b][g][e])
// =====================================================================
__global__ void mix_kernel(const float* __restrict__ wmix) {
    size_t gi = (size_t)blockIdx.x * 256 + threadIdx.x;
    int b = gi >= (size_t)ELEMS;
    size_t i = gi - (size_t)b * ELEMS;
    int e = (int)(i & 63);
    const float* wm = wmix + b * 192;
    float v = g_x6[b * 3 + 0][i] * wm[e]
            + g_x6[b * 3 + 1][i] * wm[64 + e]
            + g_x6[b * 3 + 2][i] * wm[128 + e];
    g_mixb[b][i] = sigf(v);
}

// =====================================================================
// 5. LSTM over L, warp per (t,n). grid 500 x 256
// =====================================================================
__global__ void lstm_kernel(const float* __restrict__ convw,
                            const float* __restrict__ convb) {
    __shared__ float cw[4 * 129];
    __shared__ float cb[4];
    int tid = threadIdx.x;
    for (int i = tid; i < 516; i += 256) cw[i] = convw[i];
    if (tid < 4) cb[tid] = convb[tid];
    __syncthreads();
    int gw = blockIdx.x * 8 + (tid >> 5);
    int lane = tid & 31;
    int t = gw / N_, n = gw % N_;
    int half = lane >> 4;
    int dl = (lane & 15) * 4;
    int dbase = half * 64 + dl;
    float wreg[4][4], wh[4], bb[4];
#pragma unroll
    for (int i = 0; i < 4; i++) {
#pragma unroll
        for (int q = 0; q < 4; q++) wreg[i][q] = cw[i * 129 + dbase + q];
        wh[i] = cw[i * 129 + 128];
        bb[i] = cb[i];
    }
    float h = 0.f, c = 0.f;
    for (int l = 0; l < L_; l++) {
        size_t off = (((size_t)t * L_ + l) * N_ + n) * 64 + dl;
        const float* src = half ? &g_mixb[1][off] : &g_mixb[0][off];
        float4 xin = *(const float4*)src;
        float s[4];
#pragma unroll
        for (int i = 0; i < 4; i++) {
            s[i] = xin.x * wreg[i][0] + xin.y * wreg[i][1] +
                   xin.z * wreg[i][2] + xin.w * wreg[i][3];
#pragma unroll
            for (int o = 16; o; o >>= 1)
                s[i] += __shfl_xor_sync(0xffffffffu, s[i], o);
        }
        float gi = sigf(s[0] + h * wh[0] + bb[0]);
        float gf = sigf(s[1] + h * wh[1] + bb[1]);
        float go = sigf(s[2] + h * wh[2] + bb[2]);
        float gg = tanhf(s[3] + h * wh[3] + bb[3]);
        c = gf * c + gi * gg;
        h = go * tanhf(c);
    }
    if (lane == 0) g_h[t * N_ + n] = h;
}

// =====================================================================
// 6. final projection: grid T_, block 512
// =====================================================================
__global__ void final_kernel(const float* __restrict__ finw,
                             const float* __restrict__ finb,
                             float* __restrict__ out) {
    __shared__ float hs[500];
    int t = blockIdx.x, tid = threadIdx.x;
    if (tid < 500) hs[tid] = g_h[t * N_ + tid];
    __syncthreads();
    if (tid < 500) {
        float acc = finb[tid];
        const float4* wr = (const float4*)(finw + (size_t)tid * 500);
#pragma unroll 5
        for (int m4 = 0; m4 < 125; m4++) {
            float4 wv = wr[m4];
            acc = fmaf(hs[m4 * 4 + 0], wv.x, acc);
            acc = fmaf(hs[m4 * 4 + 1], wv.y, acc);
            acc = fmaf(hs[m4 * 4 + 2], wv.z, acc);
            acc = fmaf(hs[m4 * 4 + 3], wv.w, acc);
        }
        out[t * N_ + tid] = sigf(acc);
    }
}

// ---------------- launcher ----------------
extern "C" void kernel_launch(void* const* d_in, const int* in_sizes, int n_in,
                              void* d_out, int out_size) {
    const float* stat = (const float*)d_in[0];
    const float* thre = (const float*)d_in[1];
    const float* dynn = (const float*)d_in[2];
    const int* npoi = (const int*)d_in[3];
    const int* nroad = (const int*)d_in[4];
    const int* nrec = (const int*)d_in[5];
    const float* w1 = (const float*)d_in[6];
    const float* wq = (const float*)d_in[7];
    const float* wk = (const float*)d_in[8];
    const float* wdm = (const float*)d_in[9];
    const float* wmix = (const float*)d_in[10];
    const float* convw = (const float*)d_in[11];
    const float* convb = (const float*)d_in[12];
    const float* finw = (const float*)d_in[13];
    const float* finb = (const float*)d_in[14];

    float* out = (float*)d_out;
    float* out_scores = out;                          // (T,N)       4000
    float* out_nowfinal = out + T_ * N_;              // (L,N,D)     256000
    float* out_diffs = out + T_ * N_ + L_ * N_ * D_;  // (T-1,L,N,D) 1792000

    cudaFuncSetAttribute(pass1_kernel,
                         cudaFuncAttributeMaxDynamicSharedMemorySize, P1_SMEM);

    evo_kernel<<<250, 256>>>(stat, thre, dynn, w1, out_nowfinal, out_diffs);

    for (int s = 0; s < S_; s++) {
        pass1_kernel<<<1500, 512, P1_SMEM>>>(stat, wq, wk, s);
        pass2_kernel<<<6000, 256>>>(npoi, nroad, nrec, wdm, s);
    }

    mix_kernel<<<16000, 256>>>(wmix);
    lstm_kernel<<<500, 256>>>(convw, convb);
    final_kernel<<<T_, 512>>>(finw, finb, out_scores);
}

// round 4
// speedup vs baseline: 1.0050x; 1.0050x over previous
#include <cuda_runtime.h>
#include <cuda_bf16.h>
#include <cstdint>

// Problem constants
#define T_ 8
#define L_ 8
#define N_ 500
#define D_ 64
#define K_ 12
#define S_ 2
#define RLN (L_*N_)          // 4000
#define R_ (T_*L_*N_)        // 32000 rows of (t,l,n)
#define ELEMS (R_*D_)        // 2048000

typedef unsigned long long ull;

// ---------------- scratch buffers (no allocation allowed) ----------------
__device__ float g_dyn[ELEMS];          // all_dyn (T,L,N,D)
__device__ float g_q6[6][ELEMS];        // q per (branch,graph)
__device__ float g_k6[6][ELEMS];        // k per (branch,graph)
__device__ float g_x6[6][ELEMS];        // attention output per (branch,graph)
__device__ float g_mixb[2][ELEMS];      // mixed dyn / sta
__device__ float g_h[T_*N_];            // LSTM h_last

__device__ __forceinline__ float sigf(float x) {
    return 1.f / (1.f + __expf(-x));
}

// packed dual-fp32 FMA: acc.{lo,hi} += a.{lo,hi} * b.{lo,hi}
__device__ __forceinline__ void fma2(ull& acc, ull a, ull b) {
    asm("fma.rn.f32x2 %0, %1, %2, %0;" : "+l"(acc) : "l"(a), "l"(b));
}
__device__ __forceinline__ float lo32(ull v) { return __uint_as_float((unsigned)v); }
__device__ __forceinline__ float hi32(ull v) { return __uint_as_float((unsigned)(v >> 32)); }
__device__ __forceinline__ ull dup2(float a) {
    ull r; unsigned u = __float_as_uint(a);
    asm("mov.b64 %0, {%1, %1};" : "=l"(r) : "r"(u));
    return r;
}

// =====================================================================
// 1. evolution scan: grid 250, block 256 (64 lanes x 4 groups x 4 rows)
// =====================================================================
__global__ void evo_kernel(const float* __restrict__ stat,
                           const float* __restrict__ thre,
                           const float* __restrict__ dynn,
                           const float* __restrict__ w1,
                           float* __restrict__ out_nowfinal,
                           float* __restrict__ out_diffs) {
    __shared__ float w1T[64 * 132];       // w1T[e][d], d 0..127
    __shared__ float now_s[16][64];
    __shared__ float st_s[16][64];
    __shared__ float th_s[16];
    int tid = threadIdx.x;
    for (int i = tid; i < 8192; i += 256) {
        int d = i >> 6, e = i & 63;
        w1T[e * 132 + d] = w1[i];
    }
    int e = tid & 63, grp = tid >> 6;
    int row0 = blockIdx.x * 16;
#pragma unroll
    for (int i = 0; i < 4; i++) {
        int r = grp * 4 + i;
        float v = dynn[(size_t)(row0 + r) * 64 + e];
        now_s[r][e] = v;
        g_dyn[(size_t)(row0 + r) * 64 + e] = v;   // all_dyn[t=0]
    }
    __syncthreads();

    for (int t = 1; t < T_; t++) {
        size_t base = (size_t)t * RLN + row0;
        ((float4*)st_s)[tid] = ((const float4*)(stat + base * 64))[tid];
        if (tid < 16) th_s[tid] = thre[base + tid];
        __syncthreads();

        float sum[4] = {0.f, 0.f, 0.f, 0.f};
#pragma unroll
        for (int d = 0; d < 64; d += 4) {
            float4 wn = *(float4*)&w1T[e * 132 + d];
            float4 ws = *(float4*)&w1T[e * 132 + 64 + d];
#pragma unroll
            for (int i = 0; i < 4; i++) {
                float4 nv = *(float4*)&now_s[grp * 4 + i][d];
                float4 sv = *(float4*)&st_s[grp * 4 + i][d];
                sum[i] += nv.x * wn.x + nv.y * wn.y + nv.z * wn.z + nv.w * wn.w
                        + sv.x * ws.x + sv.y * ws.y + sv.z * ws.z + sv.w * ws.w;
            }
        }
        float vals[4];
#pragma unroll
        for (int i = 0; i < 4; i++) {
            int r = grp * 4 + i;
            float th = th_s[r];
            float nv = now_s[r][e];
            float val = sigf(sum[i] * th + nv * (1.f - th));
            vals[i] = val;
            g_dyn[(base + r) * 64 + e] = val;
            out_diffs[((size_t)(t - 1) * RLN + row0 + r) * 64 + e] = val - nv;
            if (t == T_ - 1) out_nowfinal[(size_t)(row0 + r) * 64 + e] = val;
        }
        __syncthreads();
#pragma unroll
        for (int i = 0; i < 4; i++) now_s[grp * 4 + i][e] = vals[i];
        __syncthreads();
    }
}

// =====================================================================
// 2. pass1: q/k GEMM, f32x2 over COLUMN pairs, natural W, reg-dup'd A.
//    grid 3000 (6 bg x 500), block 256, 64 rows per block.
//    warp ty owns rows ty*8..+7; lane tx owns cols {2tx,2tx+1} of q and k.
// =====================================================================
#define AT_PITCH 68        // At[k][row], k=0..63, row=0..63
#define ANAT_PITCH 65      // staging, conflict-free column reads
#define W_PITCH 132        // W[k][c], c=0..127 natural (q|k)
#define P1_SMEM ((64*AT_PITCH + 64*W_PITCH) * 4)    // 17408+33792 = 51200

__global__ void __launch_bounds__(256)
pass1_kernel(const float* __restrict__ stat,
             const float* __restrict__ wq_all,
             const float* __restrict__ wk_all,
             int s) {
    extern __shared__ float sm[];
    float* At = sm;                      // [64][AT_PITCH]
    float* W_s = sm + 64 * AT_PITCH;     // [64][W_PITCH]
    float* A_nat = W_s;                  // transient staging [64][ANAT_PITCH]
    int tid = threadIdx.x;
    int bg = blockIdx.x / 500;
    int blk = blockIdx.x - bg * 500;

    const float* src;
    if (s == 0) src = (bg < 3) ? (const float*)g_dyn : stat;
    else        src = g_x6[bg];
    const float* x = src + (size_t)blk * 64 * 64;

    // phase 1: load X (64x64) into A_nat, pitch 65
    for (int i = tid; i < 4096; i += 256) {
        int row = i >> 6, k = i & 63;
        A_nat[row * ANAT_PITCH + k] = x[i];
    }
    __syncthreads();
    // phase 2: transpose into At[k][row]
    {
        int k = tid & 63, rg = tid >> 6;
#pragma unroll
        for (int r16 = 0; r16 < 16; r16++) {
            int row = rg * 16 + r16;
            At[k * AT_PITCH + row] = A_nat[row * ANAT_PITCH + k];
        }
    }
    __syncthreads();
    // phase 3: stage natural weights (overwrites A_nat region)
    {
        const float4* wq4 = (const float4*)(wq_all + (size_t)(bg * 2 + s) * 4096);
        const float4* wk4 = (const float4*)(wk_all + (size_t)(bg * 2 + s) * 4096);
        for (int i = tid; i < 2048; i += 256) {
            int half = i >> 10, idx = i & 1023;
            int k = idx >> 4, c4 = (idx & 15) << 2;
            float4 v = half ? wk4[idx] : wq4[idx];
            *(float4*)&W_s[k * W_PITCH + half * 64 + c4] = v;
        }
    }
    __syncthreads();

    int tx = tid & 31, ty = tid >> 5;   // ty: row group of 8
    ull acc[8][2];                      // [row][q/k colpair]
#pragma unroll
    for (int r = 0; r < 8; r++) { acc[r][0] = 0ull; acc[r][1] = 0ull; }

#pragma unroll 4
    for (int k = 0; k < 64; k++) {
        float4 a0 = *(const float4*)&At[k * AT_PITCH + ty * 8];      // broadcast
        float4 a1 = *(const float4*)&At[k * AT_PITCH + ty * 8 + 4];
        const ull* wrow = (const ull*)&W_s[k * W_PITCH];
        ull wq2 = wrow[tx];          // q cols (2tx, 2tx+1)
        ull wk2 = wrow[tx + 32];     // k cols (2tx, 2tx+1)
        ull ad[8];
        ad[0] = dup2(a0.x); ad[1] = dup2(a0.y); ad[2] = dup2(a0.z); ad[3] = dup2(a0.w);
        ad[4] = dup2(a1.x); ad[5] = dup2(a1.y); ad[6] = dup2(a1.z); ad[7] = dup2(a1.w);
#pragma unroll
        for (int r = 0; r < 8; r++) {
            fma2(acc[r][0], ad[r], wq2);
            fma2(acc[r][1], ad[r], wk2);
        }
    }

    float* qdst = g_q6[bg];
    float* kdst = g_k6[bg];
    size_t rowbase = (size_t)blk * 64 + ty * 8;
#pragma unroll
    for (int r = 0; r < 8; r++) {
        size_t ro = (rowbase + r) * 64 + 2 * tx;
        *(float2*)&qdst[ro] = make_float2(lo32(acc[r][0]), hi32(acc[r][0]));
        *(float2*)&kdst[ro] = make_float2(lo32(acc[r][1]), hi32(acc[r][1]));
    }
}

// =====================================================================
// 3. pass2: gather + softmax attention + wd + sigmoid. grid 6000, block 256.
//    Phase A: 16-lane x 4-elem layout; neighbor k rows HELD IN REGISTERS.
//    Phase B: f32x2 GEMM vs natural wd col-pairs.
// =====================================================================
#define OD_PITCH 68
__global__ void __launch_bounds__(256)
pass2_kernel(const int* __restrict__ n0,
             const int* __restrict__ n1,
             const int* __restrict__ n2,
             const float* __restrict__ wd_all,
             int s) {
    __shared__ float wd_s[64 * 64];              // natural
    __shared__ float2 outD[8][4][OD_PITCH];      // dup'd attention output
    int tid = threadIdx.x;
    int bg = blockIdx.x / 1000;
    int blk = blockIdx.x - bg * 1000;
    int gi3 = bg % 3;
    const int* neigh = (gi3 == 0) ? n0 : (gi3 == 1) ? n1 : n2;
    const float* wd = wd_all + (size_t)(bg * 2 + s) * 4096;

    for (int i = tid; i < 4096; i += 256) wd_s[i] = wd[i];
    __syncthreads();

    int w = tid >> 5, lane = tid & 31;
    int half = lane >> 4, l16 = lane & 15;
    const float* qb = g_q6[bg];
    const float* kb = g_k6[bg];

    // Phase A: 4 rows per warp as 2 pairs (one row per 16-lane half)
#pragma unroll
    for (int pr = 0; pr < 2; pr++) {
        int r = pr * 2 + half;
        int rowid = blk * 32 + w * 4 + r;
        int tl = rowid / N_;
        int n = rowid - tl * N_;
        const float* krow_base = kb + (size_t)tl * N_ * 64;
        float4 q = *(const float4*)&qb[(size_t)rowid * 64 + l16 * 4];
        float dots[K_];
        float4 kv[K_];
#pragma unroll
        for (int j = 0; j < K_; j++) {
            int nb = __ldg(&neigh[n * K_ + j]);
            kv[j] = *(const float4*)&krow_base[(size_t)nb * 64 + l16 * 4];
            float d = q.x * kv[j].x + q.y * kv[j].y + q.z * kv[j].z + q.w * kv[j].w;
            d += __shfl_xor_sync(0xffffffffu, d, 8);
            d += __shfl_xor_sync(0xffffffffu, d, 4);
            d += __shfl_xor_sync(0xffffffffu, d, 2);
            d += __shfl_xor_sync(0xffffffffu, d, 1);
            dots[j] = d;
        }
        float m = dots[0];
#pragma unroll
        for (int j = 1; j < K_; j++) m = fmaxf(m, dots[j]);
        float ssum = 0.f;
#pragma unroll
        for (int j = 0; j < K_; j++) {
            dots[j] = __expf(dots[j] - m);
            ssum += dots[j];
        }
        float inv = 1.f / ssum;
        float4 o = q;
#pragma unroll
        for (int j = 0; j < K_; j++) {
            float a = dots[j] * inv;
            o.x = fmaf(a, kv[j].x, o.x);
            o.y = fmaf(a, kv[j].y, o.y);
            o.z = fmaf(a, kv[j].z, o.z);
            o.w = fmaf(a, kv[j].w, o.w);
        }
        float2* ob = &outD[w][r][l16 * 4];
        ob[0] = make_float2(o.x, o.x);
        ob[1] = make_float2(o.y, o.y);
        ob[2] = make_float2(o.z, o.z);
        ob[3] = make_float2(o.w, o.w);
    }
    __syncwarp();

    // Phase B: out @ wd with f32x2; lane owns cols (2*lane, 2*lane+1), 4 rows
    ull acc2[4] = {0ull, 0ull, 0ull, 0ull};
#pragma unroll 8
    for (int d = 0; d < 64; d += 2) {
        ull w0 = *(const ull*)&wd_s[d * 64 + lane * 2];
        ull w1 = *(const ull*)&wd_s[(d + 1) * 64 + lane * 2];
#pragma unroll
        for (int r = 0; r < 4; r++) {
            ulonglong2 ov = *(const ulonglong2*)&outD[w][r][d];
            fma2(acc2[r], ov.x, w0);
            fma2(acc2[r], ov.y, w1);
        }
    }
    float* xdst = g_x6[bg];
#pragma unroll
    for (int r = 0; r < 4; r++) {
        int rowid = blk * 32 + w * 4 + r;
        float2 v = make_float2(sigf(lo32(acc2[r])), sigf(hi32(acc2[r])));
        *(float2*)&xdst[(size_t)rowid * 64 + lane * 2] = v;
    }
}

// =====================================================================
// 4. mix: g_mixb[b] = sigmoid(sum_g x6[b*3+g] * wmix[b][g][e])
// =====================================================================
__global__ void mix_kernel(const float* __restrict__ wmix) {
    size_t gi = (size_t)blockIdx.x * 256 + threadIdx.x;
    int b = gi >= (size_t)ELEMS;
    size_t i = gi - (size_t)b * ELEMS;
    int e = (int)(i & 63);
    const float* wm = wmix + b * 192;
    float v = g_x6[b * 3 + 0][i] * wm[e]
            + g_x6[b * 3 + 1][i] * wm[64 + e]
            + g_x6[b * 3 + 2][i] * wm[128 + e];
    g_mixb[b][i] = sigf(v);
}

// =====================================================================
// 5. LSTM over L, warp per (t,n). grid 500 x 256
// =====================================================================
__global__ void lstm_kernel(const float* __restrict__ convw,
                            const float* __restrict__ convb) {
    __shared__ float cw[4 * 129];
    __shared__ float cb[4];
    int tid = threadIdx.x;
    for (int i = tid; i < 516; i += 256) cw[i] = convw[i];
    if (tid < 4) cb[tid] = convb[tid];
    __syncthreads();
    int gw = blockIdx.x * 8 + (tid >> 5);
    int lane = tid & 31;
    int t = gw / N_, n = gw % N_;
    int half = lane >> 4;
    int dl = (lane & 15) * 4;
    int dbase = half * 64 + dl;
    float wreg[4][4], wh[4], bb[4];
#pragma unroll
    for (int i = 0; i < 4; i++) {
#pragma unroll
        for (int q = 0; q < 4; q++) wreg[i][q] = cw[i * 129 + dbase + q];
        wh[i] = cw[i * 129 + 128];
        bb[i] = cb[i];
    }
    float h = 0.f, c = 0.f;
    for (int l = 0; l < L_; l++) {
        size_t off = (((size_t)t * L_ + l) * N_ + n) * 64 + dl;
        const float* src = half ? &g_mixb[1][off] : &g_mixb[0][off];
        float4 xin = *(const float4*)src;
        float s[4];
#pragma unroll
        for (int i = 0; i < 4; i++) {
            s[i] = xin.x * wreg[i][0] + xin.y * wreg[i][1] +
                   xin.z * wreg[i][2] + xin.w * wreg[i][3];
#pragma unroll
            for (int o = 16; o; o >>= 1)
                s[i] += __shfl_xor_sync(0xffffffffu, s[i], o);
        }
        float gi = sigf(s[0] + h * wh[0] + bb[0]);
        float gf = sigf(s[1] + h * wh[1] + bb[1]);
        float go = sigf(s[2] + h * wh[2] + bb[2]);
        float gg = tanhf(s[3] + h * wh[3] + bb[3]);
        c = gf * c + gi * gg;
        h = go * tanhf(c);
    }
    if (lane == 0) g_h[t * N_ + n] = h;
}

// =====================================================================
// 6. final projection: grid T_, block 512
// =====================================================================
__global__ void final_kernel(const float* __restrict__ finw,
                             const float* __restrict__ finb,
                             float* __restrict__ out) {
    __shared__ float hs[500];
    int t = blockIdx.x, tid = threadIdx.x;
    if (tid < 500) hs[tid] = g_h[t * N_ + tid];
    __syncthreads();
    if (tid < 500) {
        float acc = finb[tid];
        const float4* wr = (const float4*)(finw + (size_t)tid * 500);
#pragma unroll 5
        for (int m4 = 0; m4 < 125; m4++) {
            float4 wv = wr[m4];
            acc = fmaf(hs[m4 * 4 + 0], wv.x, acc);
            acc = fmaf(hs[m4 * 4 + 1], wv.y, acc);
            acc = fmaf(hs[m4 * 4 + 2], wv.z, acc);
            acc = fmaf(hs[m4 * 4 + 3], wv.w, acc);
        }
        out[t * N_ + tid] = sigf(acc);
    }
}

// ---------------- launcher ----------------
extern "C" void kernel_launch(void* const* d_in, const int* in_sizes, int n_in,
                              void* d_out, int out_size) {
    const float* stat = (const float*)d_in[0];
    const float* thre = (const float*)d_in[1];
    const float* dynn = (const float*)d_in[2];
    const int* npoi = (const int*)d_in[3];
    const int* nroad = (const int*)d_in[4];
    const int* nrec = (const int*)d_in[5];
    const float* w1 = (const float*)d_in[6];
    const float* wq = (const float*)d_in[7];
    const float* wk = (const float*)d_in[8];
    const float* wdm = (const float*)d_in[9];
    const float* wmix = (const float*)d_in[10];
    const float* convw = (const float*)d_in[11];
    const float* convb = (const float*)d_in[12];
    const float* finw = (const float*)d_in[13];
    const float* finb = (const float*)d_in[14];

    float* out = (float*)d_out;
    float* out_scores = out;                          // (T,N)       4000
    float* out_nowfinal = out + T_ * N_;              // (L,N,D)     256000
    float* out_diffs = out + T_ * N_ + L_ * N_ * D_;  // (T-1,L,N,D) 1792000

    cudaFuncSetAttribute(pass1_kernel,
                         cudaFuncAttributeMaxDynamicSharedMemorySize, P1_SMEM);

    evo_kernel<<<250, 256>>>(stat, thre, dynn, w1, out_nowfinal, out_diffs);

    for (int s = 0; s < S_; s++) {
        pass1_kernel<<<3000, 256, P1_SMEM>>>(stat, wq, wk, s);
        pass2_kernel<<<6000, 256>>>(npoi, nroad, nrec, wdm, s);
    }

    mix_kernel<<<16000, 256>>>(wmix);
    lstm_kernel<<<500, 256>>>(convw, convb);
    final_kernel<<<T_, 512>>>(finw, finb, out_scores);
}